// round 7
// baseline (speedup 1.0000x reference)
#include <cuda_runtime.h>
#include <cstdint>

// Problem constants
#define BB   8
#define C    256
#define HH   64
#define WW   64
#define K2   9
#define COUT 256
#define PLANE (HH*WW)      // 4096
#define NPIX  (BB*PLANE)   // 32768
#define KJ   2304          // C*K2

// ---------------------------------------------------------------------------
// Static device scratch
// ---------------------------------------------------------------------------
__device__ float g_mw0[BB*K2*PLANE];
__device__ float g_mw1[BB*K2*PLANE];
__device__ float g_mw2[BB*K2*PLANE];
__device__ float g_mw3[BB*K2*PLANE];
__device__ int   g_mi0[BB*K2*PLANE];
__device__ int   g_mi1[BB*K2*PLANE];
__device__ int   g_mi2[BB*K2*PLANE];
__device__ int   g_mi3[BB*K2*PLANE];

// Weights bf16, 2 planes: [plane][o][j]  (plane0=hi, plane1=lo), j = k9*256+c
__device__ __align__(16) unsigned short g_A[2 * COUT * KJ];

// ---------------------------------------------------------------------------
__device__ __forceinline__ void bsplit(float v, unsigned &h, unsigned &l) {
    unsigned u = __float_as_uint(v);
    unsigned r = (u + 0x7FFFu + ((u >> 16) & 1u)) & 0xFFFF0000u;
    h = r >> 16;
    float d = v - __uint_as_float(r);
    unsigned ud = __float_as_uint(d);
    l = (ud + 0x7FFFu + ((ud >> 16) & 1u)) >> 16;
}

// ---------------------------------------------------------------------------
// Kernel 1: weight prep
// ---------------------------------------------------------------------------
__global__ void aprep_kernel(const float* __restrict__ w) {
    int idx = blockIdx.x * 256 + threadIdx.x;
    if (idx >= COUT * KJ) return;
    int o = idx / KJ;
    int j = idx - o * KJ;
    int c = j & 255, k9 = j >> 8;
    float v = w[((o << 8) + c) * 9 + k9];
    unsigned h, l; bsplit(v, h, l);
    g_A[idx]             = (unsigned short)h;
    g_A[COUT*KJ + idx]   = (unsigned short)l;
}

// ---------------------------------------------------------------------------
// Kernel 2: bilinear metadata
// ---------------------------------------------------------------------------
__global__ void meta_kernel(const float* __restrict__ off) {
    int e = blockIdx.x * 256 + threadIdx.x;
    if (e >= BB*K2*PLANE) return;
    int p  = e & (PLANE - 1);
    int bk = e >> 12;
    int k  = bk % 9;
    int b  = bk / 9;
    int ho = p >> 6;
    int wo = p & 63;

    float dy = off[((size_t)(b*18 + 2*k    ) << 12) + p];
    float dx = off[((size_t)(b*18 + 2*k + 1) << 12) + p];

    float py = (float)(ho - 1 + (k / 3)) + dy;
    float px = (float)(wo - 1 + (k % 3)) + dx;

    float y0f = floorf(py), x0f = floorf(px);
    float fy = py - y0f, fx = px - x0f;
    int   y0 = (int)y0f,  x0 = (int)x0f;

    float wy[2] = {1.0f - fy, fy};
    float wx[2] = {1.0f - fx, fx};
    int   ys[2] = {y0, y0 + 1};
    int   xs[2] = {x0, x0 + 1};

    float mw[4]; int mi[4];
    #pragma unroll
    for (int jy = 0; jy < 2; jy++)
        #pragma unroll
        for (int jx = 0; jx < 2; jx++) {
            int jj = jy*2 + jx;
            int cy = ys[jy], cx = xs[jx];
            bool valid = (cy >= 0) && (cy < HH) && (cx >= 0) && (cx < WW);
            float wgt = valid ? wy[jy] * wx[jx] : 0.0f;
            int iy = min(max(cy, 0), HH - 1);
            int ix = min(max(cx, 0), WW - 1);
            mw[jj] = wgt;
            mi[jj] = iy * WW + ix;
        }
    g_mw0[e] = mw[0]; g_mw1[e] = mw[1]; g_mw2[e] = mw[2]; g_mw3[e] = mw[3];
    g_mi0[e] = mi[0]; g_mi1[e] = mi[1]; g_mi2[e] = mi[2]; g_mi3[e] = mi[3];
}

// ---------------------------------------------------------------------------
// Kernel 3: fused gather + 3-pass split GEMM, gather pipelined through MMA
//   CTA: M=256 x N=128 pixels, 512 threads (16 warps, 4Mx4N).
//   36 stages of BK=64. smem: A 2x64KB | B 2x32KB = 192KB.
//   Ordering: [sync] STS B(s+1) | MMA stage s + gather LDG for s+2
//             [sync] cp.async A(s+2)   <-- barrier protects A slot WAR
// ---------------------------------------------------------------------------
#define SWZ(x) ((x) ^ (((x) >> 3) & 0x70))
#define NST2   36
#define SM_TOTAL 196608

static __device__ __forceinline__ uint32_t smem_u32(const void* p) {
    uint32_t a;
    asm("{ .reg .u64 t; cvta.to.shared.u64 t, %1; cvt.u32.u64 %0, t; }"
        : "=r"(a) : "l"(p));
    return a;
}
static __device__ __forceinline__ void cp16(uint32_t dst, const void* src) {
    asm volatile("cp.async.cg.shared.global [%0], [%1], 16;\n"
                 :: "r"(dst), "l"(src));
}
#define LDSM4(r0, r1, r2, r3, a)                                              \
    asm volatile("ldmatrix.sync.aligned.m8n8.x4.shared.b16 {%0,%1,%2,%3}, [%4];" \
                 : "=r"(r0), "=r"(r1), "=r"(r2), "=r"(r3) : "r"(a))
#define MMA16816(d, a0, a1, a2, a3, b0, b1)                                   \
    asm volatile("mma.sync.aligned.m16n8k16.row.col.f32.bf16.bf16.f32 "       \
                 "{%0,%1,%2,%3}, {%4,%5,%6,%7}, {%8,%9}, {%0,%1,%2,%3};"      \
                 : "+f"((d)[0]), "+f"((d)[1]), "+f"((d)[2]), "+f"((d)[3])     \
                 : "r"(a0), "r"(a1), "r"(a2), "r"(a3), "r"(b0), "r"(b1))
#define STS128(a, v)                                                          \
    asm volatile("st.shared.v4.b32 [%0], {%1,%2,%3,%4};"                      \
                 :: "r"(a), "r"((v).x), "r"((v).y), "r"((v).z), "r"((v).w) : "memory")

// A tiles (hi+lo, 64KB) for stage s via cp.async into slot s&1
static __device__ __forceinline__ void produceA(int s, int tid, uint32_t sb) {
    uint32_t base = sb + (s & 1) * 65536;
    const char* gA = (const char*)(g_A + (size_t)s * 64);
    #pragma unroll
    for (int pl = 0; pl < 2; pl++) {
        uint32_t dA = base + pl * 32768;
        const char* gp = gA + (size_t)pl * (COUT * KJ * 2);
        #pragma unroll
        for (int i = 0; i < 4; i++) {
            int id = tid + i * 512;
            int row = id >> 3;
            int kb  = (id & 7) << 4;
            cp16(dA + SWZ(row * 128 + kb), gp + (size_t)row * (KJ * 2) + kb);
        }
    }
    asm volatile("cp.async.commit_group;" ::: "memory");
}

// gather one 4-channel chunk (16 LDG) -> 2 hi + 2 lo packed uints
static __device__ __forceinline__ void gchunk(const float* xp,
                                              int i0, int i1, int i2, int i3,
                                              float w0, float w1, float w2, float w3,
                                              unsigned &h0, unsigned &h1,
                                              unsigned &l0, unsigned &l1) {
    const float* x1 = xp + 4096;
    const float* x2 = xp + 8192;
    const float* x3 = xp + 12288;
    float v0 = w0*xp[i0] + w1*xp[i1] + w2*xp[i2] + w3*xp[i3];
    float v1 = w0*x1[i0] + w1*x1[i1] + w2*x1[i2] + w3*x1[i3];
    float v2 = w0*x2[i0] + w1*x2[i1] + w2*x2[i2] + w3*x2[i3];
    float v3 = w0*x3[i0] + w1*x3[i1] + w2*x3[i2] + w3*x3[i3];
    unsigned u0 = __float_as_uint(v0), u1 = __float_as_uint(v1);
    unsigned u2 = __float_as_uint(v2), u3 = __float_as_uint(v3);
    float e0 = v0 - __uint_as_float(u0 & 0xFFFF0000u);
    float e1 = v1 - __uint_as_float(u1 & 0xFFFF0000u);
    float e2 = v2 - __uint_as_float(u2 & 0xFFFF0000u);
    float e3 = v3 - __uint_as_float(u3 & 0xFFFF0000u);
    h0 = __byte_perm(u0, u1, 0x7632);
    h1 = __byte_perm(u2, u3, 0x7632);
    l0 = __byte_perm(__float_as_uint(e0), __float_as_uint(e1), 0x7632);
    l1 = __byte_perm(__float_as_uint(e2), __float_as_uint(e3), 0x7632);
}

__global__ __launch_bounds__(512, 1)
void dconv_fused(const float* __restrict__ x, float* __restrict__ out) {
    extern __shared__ char smem[];
    uint32_t sb = smem_u32(smem);
    int tid = threadIdx.x;
    int wid = tid >> 5, lid = tid & 31;
    const int pt0 = blockIdx.x << 7;
    const int b = pt0 >> 12;
    const int pin = pt0 & 4095;
    const int pxl = tid & 127;
    const int cg  = tid >> 7;                       // 0..3

    const int wm0 = (wid & 3) << 6;
    const int wn0 = (wid >> 2) << 5;
    const int boff = pxl * 128 + (cg << 5);
    const float* xg = x + ((size_t)b << 20) + ((size_t)(cg << 4) << 12);

    float acc[4][4][4];
    #pragma unroll
    for (int i = 0; i < 4; i++)
        #pragma unroll
        for (int j = 0; j < 4; j++)
            #pragma unroll
            for (int r = 0; r < 4; r++) acc[i][j][r] = 0.0f;

    unsigned ch[8], cl[8];                          // carried B gather (next stage)

    // ---- prologue ----
    // stage 0 (k9=0, cb=0): gather + STS directly into B slot 0
    {
        int e = ((b * 9 + 0) << 12) + pin + pxl;
        float w0 = g_mw0[e], w1 = g_mw1[e], w2 = g_mw2[e], w3 = g_mw3[e];
        int   i0 = g_mi0[e], i1 = g_mi1[e], i2 = g_mi2[e], i3 = g_mi3[e];
        #pragma unroll
        for (int q = 0; q < 4; q++)
            gchunk(xg + ((size_t)(q << 2) << 12), i0, i1, i2, i3, w0, w1, w2, w3,
                   ch[2*q], ch[2*q + 1], cl[2*q], cl[2*q + 1]);
        uint32_t sBh = sb + 131072;                 // slot 0
        uint32_t sBl = sBh + 16384;
        STS128(sBh + SWZ(boff),      make_uint4(ch[0], ch[1], ch[2], ch[3]));
        STS128(sBh + SWZ(boff + 16), make_uint4(ch[4], ch[5], ch[6], ch[7]));
        STS128(sBl + SWZ(boff),      make_uint4(cl[0], cl[1], cl[2], cl[3]));
        STS128(sBl + SWZ(boff + 16), make_uint4(cl[4], cl[5], cl[6], cl[7]));
    }
    // stage 1 (k9=0, cb=64): gather into carry regs (STS at iter 0 top)
    {
        int e = ((b * 9 + 0) << 12) + pin + pxl;
        float w0 = g_mw0[e], w1 = g_mw1[e], w2 = g_mw2[e], w3 = g_mw3[e];
        int   i0 = g_mi0[e], i1 = g_mi1[e], i2 = g_mi2[e], i3 = g_mi3[e];
        #pragma unroll
        for (int q = 0; q < 4; q++)
            gchunk(xg + ((size_t)(64 + (q << 2)) << 12), i0, i1, i2, i3, w0, w1, w2, w3,
                   ch[2*q], ch[2*q + 1], cl[2*q], cl[2*q + 1]);
    }
    produceA(0, tid, sb);
    produceA(1, tid, sb);

    for (int s = 0; s < NST2; s++) {
        if (s == NST2 - 1)
            asm volatile("cp.async.wait_group 0;" ::: "memory");
        else
            asm volatile("cp.async.wait_group 1;" ::: "memory");
        __syncthreads();

        // STS carried B(s+1) into slot (s+1)&1 (iter s-1 readers of that slot
        // are fenced by the barrier above; iter s reads slot s&1)
        if (s + 1 < NST2) {
            uint32_t sBh = sb + 131072 + ((s + 1) & 1) * 32768;
            uint32_t sBl = sBh + 16384;
            STS128(sBh + SWZ(boff),      make_uint4(ch[0], ch[1], ch[2], ch[3]));
            STS128(sBh + SWZ(boff + 16), make_uint4(ch[4], ch[5], ch[6], ch[7]));
            STS128(sBl + SWZ(boff),      make_uint4(cl[0], cl[1], cl[2], cl[3]));
            STS128(sBl + SWZ(boff + 16), make_uint4(cl[4], cl[5], cl[6], cl[7]));
        }

        // gather metadata for stage s+2
        const bool do_g = (s + 2 < NST2);
        float w0 = 0.f, w1 = 0.f, w2 = 0.f, w3 = 0.f;
        int i0 = 0, i1 = 0, i2 = 0, i3 = 0;
        const float* xc = xg;
        if (do_g) {
            int s2 = s + 2;
            int e = ((b * 9 + (s2 >> 2)) << 12) + pin + pxl;
            w0 = g_mw0[e]; w1 = g_mw1[e]; w2 = g_mw2[e]; w3 = g_mw3[e];
            i0 = g_mi0[e]; i1 = g_mi1[e]; i2 = g_mi2[e]; i3 = g_mi3[e];
            xc = xg + ((size_t)((s2 & 3) << 6) << 12);
        }

        uint32_t base = sb + (s & 1) * 65536;
        uint32_t sAh = base, sAl = base + 32768;
        uint32_t sBh = sb + 131072 + (s & 1) * 32768;
        uint32_t sBl = sBh + 16384;
        int lr = lid & 15, lc = (lid >> 4) << 4;

        #pragma unroll
        for (int ks = 0; ks < 4; ks++) {
            int kb = ks << 5;
            // issue gather chunk loads early (hidden under the MMA below)
            float ga0=0,ga1=0,ga2=0,ga3=0, gb0=0,gb1=0,gb2=0,gb3=0;
            float gc0=0,gc1=0,gc2=0,gc3=0, gd0=0,gd1=0,gd2=0,gd3=0;
            if (do_g) {
                const float* xp = xc + ((size_t)(ks << 2) << 12);
                const float* x1p = xp + 4096;
                const float* x2p = xp + 8192;
                const float* x3p = xp + 12288;
                ga0 = xp[i0];  ga1 = xp[i1];  ga2 = xp[i2];  ga3 = xp[i3];
                gb0 = x1p[i0]; gb1 = x1p[i1]; gb2 = x1p[i2]; gb3 = x1p[i3];
                gc0 = x2p[i0]; gc1 = x2p[i1]; gc2 = x2p[i2]; gc3 = x2p[i3];
                gd0 = x3p[i0]; gd1 = x3p[i1]; gd2 = x3p[i2]; gd3 = x3p[i3];
            }

            uint32_t bh[2][4], bl[2][4];
            #pragma unroll
            for (int bt = 0; bt < 2; bt++) {
                uint32_t bd = sBh + SWZ((wn0 + (bt << 4) + lr) * 128 + kb + lc);
                LDSM4(bh[bt][0], bh[bt][1], bh[bt][2], bh[bt][3], bd);
            }
            #pragma unroll
            for (int bt = 0; bt < 2; bt++) {
                uint32_t bd = sBl + SWZ((wn0 + (bt << 4) + lr) * 128 + kb + lc);
                LDSM4(bl[bt][0], bl[bt][1], bl[bt][2], bl[bt][3], bd);
            }
            #pragma unroll
            for (int mt = 0; mt < 4; mt++) {
                uint32_t a0, a1, a2, a3;
                uint32_t ad = sAh + SWZ((wm0 + (mt << 4) + lr) * 128 + kb + lc);
                LDSM4(a0, a1, a2, a3, ad);
                #pragma unroll
                for (int n8 = 0; n8 < 4; n8++) {
                    int bt = n8 >> 1, nn = n8 & 1;
                    MMA16816(acc[mt][n8], a0, a1, a2, a3, bh[bt][nn], bh[bt][nn + 2]);
                }
                #pragma unroll
                for (int n8 = 0; n8 < 4; n8++) {
                    int bt = n8 >> 1, nn = n8 & 1;
                    MMA16816(acc[mt][n8], a0, a1, a2, a3, bl[bt][nn], bl[bt][nn + 2]);
                }
            }
            #pragma unroll
            for (int mt = 0; mt < 4; mt++) {
                uint32_t a0, a1, a2, a3;
                uint32_t ad = sAl + SWZ((wm0 + (mt << 4) + lr) * 128 + kb + lc);
                LDSM4(a0, a1, a2, a3, ad);
                #pragma unroll
                for (int n8 = 0; n8 < 4; n8++) {
                    int bt = n8 >> 1, nn = n8 & 1;
                    MMA16816(acc[mt][n8], a0, a1, a2, a3, bh[bt][nn], bh[bt][nn + 2]);
                }
            }

            // combine gather chunk -> carry regs
            if (do_g) {
                float v0 = w0*ga0 + w1*ga1 + w2*ga2 + w3*ga3;
                float v1 = w0*gb0 + w1*gb1 + w2*gb2 + w3*gb3;
                float v2 = w0*gc0 + w1*gc1 + w2*gc2 + w3*gc3;
                float v3 = w0*gd0 + w1*gd1 + w2*gd2 + w3*gd3;
                unsigned u0 = __float_as_uint(v0), u1 = __float_as_uint(v1);
                unsigned u2 = __float_as_uint(v2), u3 = __float_as_uint(v3);
                float e0 = v0 - __uint_as_float(u0 & 0xFFFF0000u);
                float e1 = v1 - __uint_as_float(u1 & 0xFFFF0000u);
                float e2 = v2 - __uint_as_float(u2 & 0xFFFF0000u);
                float e3 = v3 - __uint_as_float(u3 & 0xFFFF0000u);
                ch[2*ks]     = __byte_perm(u0, u1, 0x7632);
                ch[2*ks + 1] = __byte_perm(u2, u3, 0x7632);
                cl[2*ks]     = __byte_perm(__float_as_uint(e0), __float_as_uint(e1), 0x7632);
                cl[2*ks + 1] = __byte_perm(__float_as_uint(e2), __float_as_uint(e3), 0x7632);
            }
        }

        // WAR barrier: all warps must finish reading A slot s&1 before
        // cp.async for stage s+2 overwrites it.
        __syncthreads();
        if (s + 2 < NST2)
            produceA(s + 2, tid, sb);
    }

    // epilogue
    #pragma unroll
    for (int mt = 0; mt < 4; mt++) {
        int o = wm0 + (mt << 4) + (lid >> 2);
        float* rp = out + (((size_t)((b << 8) + o)) << 12) + pin;
        #pragma unroll
        for (int n8 = 0; n8 < 4; n8++) {
            int col = wn0 + (n8 << 3) + ((lid & 3) << 1);
            *(float2*)(rp + col)             = make_float2(acc[mt][n8][0], acc[mt][n8][1]);
            *(float2*)(rp + (8 << 12) + col) = make_float2(acc[mt][n8][2], acc[mt][n8][3]);
        }
    }
}

// ---------------------------------------------------------------------------
extern "C" void kernel_launch(void* const* d_in, const int* in_sizes, int n_in,
                              void* d_out, int out_size) {
    const float* x   = (const float*)d_in[0];
    const float* off = (const float*)d_in[1];
    const float* w   = (const float*)d_in[2];
    float* out = (float*)d_out;

    cudaFuncSetAttribute(dconv_fused,
                         cudaFuncAttributeMaxDynamicSharedMemorySize, SM_TOTAL);

    aprep_kernel<<<(COUT*KJ + 255) / 256, 256>>>(w);
    meta_kernel<<<(BB*K2*PLANE + 255) / 256, 256>>>(off);

    dconv_fused<<<NPIX / 128, 512, SM_TOTAL>>>(x, out);
}

// round 9
// speedup vs baseline: 1.2210x; 1.2210x over previous
#include <cuda_runtime.h>
#include <cstdint>

// Problem constants
#define BB   8
#define C    256
#define HH   64
#define WW   64
#define K2   9
#define COUT 256
#define PLANE (HH*WW)      // 4096
#define NPIX  (BB*PLANE)   // 32768
#define KJ   2304          // C*K2

// ---------------------------------------------------------------------------
// Static device scratch
// ---------------------------------------------------------------------------
__device__ float g_mw0[BB*K2*PLANE];
__device__ float g_mw1[BB*K2*PLANE];
__device__ float g_mw2[BB*K2*PLANE];
__device__ float g_mw3[BB*K2*PLANE];
__device__ int   g_mi0[BB*K2*PLANE];
__device__ int   g_mi1[BB*K2*PLANE];
__device__ int   g_mi2[BB*K2*PLANE];
__device__ int   g_mi3[BB*K2*PLANE];

// Weights bf16, 2 planes: [plane][o][j]  (plane0=hi, plane1=lo), j = k9*256+c
__device__ __align__(16) unsigned short g_A[2 * COUT * KJ];

// x transposed to NHWC: g_xt[((b*4096 + pix) * 256) + c]
__device__ __align__(16) float g_xt[(size_t)NPIX * C];     // 134 MB

// ---------------------------------------------------------------------------
__device__ __forceinline__ void bsplit(float v, unsigned &h, unsigned &l) {
    unsigned u = __float_as_uint(v);
    unsigned r = (u + 0x7FFFu + ((u >> 16) & 1u)) & 0xFFFF0000u;
    h = r >> 16;
    float d = v - __uint_as_float(r);
    unsigned ud = __float_as_uint(d);
    l = (ud + 0x7FFFu + ((ud >> 16) & 1u)) >> 16;
}

// ---------------------------------------------------------------------------
// Kernel 1: weight prep
// ---------------------------------------------------------------------------
__global__ void aprep_kernel(const float* __restrict__ w) {
    int idx = blockIdx.x * 256 + threadIdx.x;
    if (idx >= COUT * KJ) return;
    int o = idx / KJ;
    int j = idx - o * KJ;
    int c = j & 255, k9 = j >> 8;
    float v = w[((o << 8) + c) * 9 + k9];
    unsigned h, l; bsplit(v, h, l);
    g_A[idx]             = (unsigned short)h;
    g_A[COUT*KJ + idx]   = (unsigned short)l;
}

// ---------------------------------------------------------------------------
// Kernel 2: bilinear metadata
// ---------------------------------------------------------------------------
__global__ void meta_kernel(const float* __restrict__ off) {
    int e = blockIdx.x * 256 + threadIdx.x;
    if (e >= BB*K2*PLANE) return;
    int p  = e & (PLANE - 1);
    int bk = e >> 12;
    int k  = bk % 9;
    int b  = bk / 9;
    int ho = p >> 6;
    int wo = p & 63;

    float dy = off[((size_t)(b*18 + 2*k    ) << 12) + p];
    float dx = off[((size_t)(b*18 + 2*k + 1) << 12) + p];

    float py = (float)(ho - 1 + (k / 3)) + dy;
    float px = (float)(wo - 1 + (k % 3)) + dx;

    float y0f = floorf(py), x0f = floorf(px);
    float fy = py - y0f, fx = px - x0f;
    int   y0 = (int)y0f,  x0 = (int)x0f;

    float wy[2] = {1.0f - fy, fy};
    float wx[2] = {1.0f - fx, fx};
    int   ys[2] = {y0, y0 + 1};
    int   xs[2] = {x0, x0 + 1};

    float mw[4]; int mi[4];
    #pragma unroll
    for (int jy = 0; jy < 2; jy++)
        #pragma unroll
        for (int jx = 0; jx < 2; jx++) {
            int jj = jy*2 + jx;
            int cy = ys[jy], cx = xs[jx];
            bool valid = (cy >= 0) && (cy < HH) && (cx >= 0) && (cx < WW);
            float wgt = valid ? wy[jy] * wx[jx] : 0.0f;
            int iy = min(max(cy, 0), HH - 1);
            int ix = min(max(cx, 0), WW - 1);
            mw[jj] = wgt;
            mi[jj] = iy * WW + ix;
        }
    g_mw0[e] = mw[0]; g_mw1[e] = mw[1]; g_mw2[e] = mw[2]; g_mw3[e] = mw[3];
    g_mi0[e] = mi[0]; g_mi1[e] = mi[1]; g_mi2[e] = mi[2]; g_mi3[e] = mi[3];
}

// ---------------------------------------------------------------------------
// Kernel 3: NCHW -> NHWC transpose (32x32 tiles via smem)
// ---------------------------------------------------------------------------
__global__ __launch_bounds__(256)
void xt_kernel(const float* __restrict__ x) {
    __shared__ float ts[32][33];
    int bid = blockIdx.x;
    int ct = (bid & 7) << 5;                 // channel tile base
    int pt = ((bid >> 3) & 127) << 5;        // pixel tile base
    int b  = bid >> 10;
    int l0 = threadIdx.x & 31;
    int l1 = threadIdx.x >> 5;               // 0..7
    const float* xb = x + ((size_t)b << 20);
    #pragma unroll
    for (int r = 0; r < 4; r++) {
        int c = ct + l1 + r * 8;
        ts[l1 + r * 8][l0] = xb[((size_t)c << 12) + pt + l0];
    }
    __syncthreads();
    float* xo = g_xt + (((size_t)(b << 12) + pt) << 8) + ct;
    #pragma unroll
    for (int r = 0; r < 4; r++) {
        int p = l1 + r * 8;
        xo[((size_t)p << 8) + l0] = ts[l0][p];
    }
}

// ---------------------------------------------------------------------------
// Kernel 4: fused warp-specialized GEMM
//   CTA: M=256 x N=128 pixels. 640 threads:
//     warps 0-15: MMA consumers (4Mx4N, warp tile 64x32)
//     warps 16-19: producers (cp.async A + NHWC gather B for stage s+1)
//   36 stages of BK=64. smem: A 2x64KB | B 2x32KB = 192KB.
// ---------------------------------------------------------------------------
#define SWZ(x) ((x) ^ (((x) >> 3) & 0x70))
#define NST2   36
#define SM_TOTAL 196608

static __device__ __forceinline__ uint32_t smem_u32(const void* p) {
    uint32_t a;
    asm("{ .reg .u64 t; cvta.to.shared.u64 t, %1; cvt.u32.u64 %0, t; }"
        : "=r"(a) : "l"(p));
    return a;
}
static __device__ __forceinline__ void cp16(uint32_t dst, const void* src) {
    asm volatile("cp.async.cg.shared.global [%0], [%1], 16;\n"
                 :: "r"(dst), "l"(src));
}
#define LDSM4(r0, r1, r2, r3, a)                                              \
    asm volatile("ldmatrix.sync.aligned.m8n8.x4.shared.b16 {%0,%1,%2,%3}, [%4];" \
                 : "=r"(r0), "=r"(r1), "=r"(r2), "=r"(r3) : "r"(a))
#define MMA16816(d, a0, a1, a2, a3, b0, b1)                                   \
    asm volatile("mma.sync.aligned.m16n8k16.row.col.f32.bf16.bf16.f32 "       \
                 "{%0,%1,%2,%3}, {%4,%5,%6,%7}, {%8,%9}, {%0,%1,%2,%3};"      \
                 : "+f"((d)[0]), "+f"((d)[1]), "+f"((d)[2]), "+f"((d)[3])     \
                 : "r"(a0), "r"(a1), "r"(a2), "r"(a3), "r"(b0), "r"(b1))
#define STS128(a, v)                                                          \
    asm volatile("st.shared.v4.b32 [%0], {%1,%2,%3,%4};"                      \
                 :: "r"(a), "r"((v).x), "r"((v).y), "r"((v).z), "r"((v).w) : "memory")

// Producer: build stage sn (A via cp.async, B via NHWC gather) into slot sn&1
static __device__ __forceinline__ void produceP(int sn, int t2, uint32_t sb,
                                                int b, int pin) {
    // ---- A (hi+lo, 64 KB) ----
    {
        uint32_t dst0 = sb + (sn & 1) * 65536;
        #pragma unroll
        for (int i = 0; i < 32; i++) {
            int id = t2 + (i << 7);          // 0..4095
            int pl = id >> 11;
            int idp = id & 2047;
            int row = idp >> 3;
            int kb = (idp & 7) << 4;
            const char* src = (const char*)g_A +
                (((size_t)(pl * COUT + row) * KJ + sn * 64) << 1) + kb;
            cp16(dst0 + pl * 32768 + SWZ(row * 128 + kb), src);
        }
        asm volatile("cp.async.commit_group;" ::: "memory");
    }
    // ---- B gather from NHWC ----
    int k9 = sn >> 2, cb = (sn & 3) << 6;
    int q = t2 & 3, pxs = t2 >> 2;           // q: 16-ch quad, pxs: 0..31
    int c0 = cb + (q << 4);
    uint32_t sBh = sb + 131072 + (sn & 1) * 32768;
    uint32_t sBl = sBh + 16384;
    const float* xb = g_xt + (((size_t)(b << 12)) << 8) + c0;

    #pragma unroll
    for (int r = 0; r < 4; r++) {
        int px = pxs + (r << 5);
        int e = ((b * 9 + k9) << 12) + pin + px;
        float w0 = g_mw0[e], w1 = g_mw1[e], w2 = g_mw2[e], w3 = g_mw3[e];
        int   i0 = g_mi0[e], i1 = g_mi1[e], i2 = g_mi2[e], i3 = g_mi3[e];
        const float4* p0 = (const float4*)(xb + ((size_t)i0 << 8));
        const float4* p1 = (const float4*)(xb + ((size_t)i1 << 8));
        const float4* p2 = (const float4*)(xb + ((size_t)i2 << 8));
        const float4* p3 = (const float4*)(xb + ((size_t)i3 << 8));
        float v[16];
        #pragma unroll
        for (int j = 0; j < 4; j++) {
            float4 a = p0[j];
            v[4*j]   = w0 * a.x; v[4*j+1] = w0 * a.y;
            v[4*j+2] = w0 * a.z; v[4*j+3] = w0 * a.w;
        }
        #pragma unroll
        for (int j = 0; j < 4; j++) {
            float4 a = p1[j];
            v[4*j]   += w1 * a.x; v[4*j+1] += w1 * a.y;
            v[4*j+2] += w1 * a.z; v[4*j+3] += w1 * a.w;
        }
        #pragma unroll
        for (int j = 0; j < 4; j++) {
            float4 a = p2[j];
            v[4*j]   += w2 * a.x; v[4*j+1] += w2 * a.y;
            v[4*j+2] += w2 * a.z; v[4*j+3] += w2 * a.w;
        }
        #pragma unroll
        for (int j = 0; j < 4; j++) {
            float4 a = p3[j];
            v[4*j]   += w3 * a.x; v[4*j+1] += w3 * a.y;
            v[4*j+2] += w3 * a.z; v[4*j+3] += w3 * a.w;
        }
        unsigned hi[8], lo[8];
        #pragma unroll
        for (int k = 0; k < 8; k++) {
            float va = v[2*k], vb = v[2*k+1];
            unsigned ua = __float_as_uint(va), ub = __float_as_uint(vb);
            float ea = va - __uint_as_float(ua & 0xFFFF0000u);
            float eb = vb - __uint_as_float(ub & 0xFFFF0000u);
            hi[k] = __byte_perm(ua, ub, 0x7632);
            lo[k] = __byte_perm(__float_as_uint(ea), __float_as_uint(eb), 0x7632);
        }
        int boff = px * 128 + (q << 5);
        STS128(sBh + SWZ(boff),      make_uint4(hi[0], hi[1], hi[2], hi[3]));
        STS128(sBh + SWZ(boff + 16), make_uint4(hi[4], hi[5], hi[6], hi[7]));
        STS128(sBl + SWZ(boff),      make_uint4(lo[0], lo[1], lo[2], lo[3]));
        STS128(sBl + SWZ(boff + 16), make_uint4(lo[4], lo[5], lo[6], lo[7]));
    }
    asm volatile("cp.async.wait_group 0;" ::: "memory");
}

__global__ __launch_bounds__(640, 1)
void dconv_fused(float* __restrict__ out) {
    extern __shared__ char smem[];
    uint32_t sb = smem_u32(smem);
    int tid = threadIdx.x;
    int wid = tid >> 5, lid = tid & 31;
    const int pt0 = blockIdx.x << 7;
    const int b = pt0 >> 12;
    const int pin = pt0 & 4095;
    const bool is_prod = (tid >= 512);
    const int t2 = tid - 512;

    // ---- prologue: producers build stage 0 ----
    if (is_prod)
        produceP(0, t2, sb, b, pin);
    __syncthreads();

    if (!is_prod) {
        const int wm0 = (wid & 3) << 6;
        const int wn0 = (wid >> 2) << 5;
        float acc[4][4][4];
        #pragma unroll
        for (int i = 0; i < 4; i++)
            #pragma unroll
            for (int j = 0; j < 4; j++)
                #pragma unroll
                for (int r = 0; r < 4; r++) acc[i][j][r] = 0.0f;

        int lr = lid & 15, lc = (lid >> 4) << 4;

        for (int s = 0; s < NST2; s++) {
            uint32_t base = sb + (s & 1) * 65536;
            uint32_t sAh = base, sAl = base + 32768;
            uint32_t sBh = sb + 131072 + (s & 1) * 32768;
            uint32_t sBl = sBh + 16384;

            #pragma unroll
            for (int ks = 0; ks < 4; ks++) {
                int kb = ks << 5;
                uint32_t bh[2][4], bl[2][4];
                #pragma unroll
                for (int bt = 0; bt < 2; bt++) {
                    uint32_t bd = sBh + SWZ((wn0 + (bt << 4) + lr) * 128 + kb + lc);
                    LDSM4(bh[bt][0], bh[bt][1], bh[bt][2], bh[bt][3], bd);
                }
                #pragma unroll
                for (int bt = 0; bt < 2; bt++) {
                    uint32_t bd = sBl + SWZ((wn0 + (bt << 4) + lr) * 128 + kb + lc);
                    LDSM4(bl[bt][0], bl[bt][1], bl[bt][2], bl[bt][3], bd);
                }
                #pragma unroll
                for (int mt = 0; mt < 4; mt++) {
                    uint32_t a0, a1, a2, a3;
                    uint32_t ad = sAh + SWZ((wm0 + (mt << 4) + lr) * 128 + kb + lc);
                    LDSM4(a0, a1, a2, a3, ad);
                    #pragma unroll
                    for (int n8 = 0; n8 < 4; n8++) {
                        int bt = n8 >> 1, nn = n8 & 1;
                        MMA16816(acc[mt][n8], a0, a1, a2, a3, bh[bt][nn], bh[bt][nn + 2]);
                    }
                    #pragma unroll
                    for (int n8 = 0; n8 < 4; n8++) {
                        int bt = n8 >> 1, nn = n8 & 1;
                        MMA16816(acc[mt][n8], a0, a1, a2, a3, bl[bt][nn], bl[bt][nn + 2]);
                    }
                }
                #pragma unroll
                for (int mt = 0; mt < 4; mt++) {
                    uint32_t a0, a1, a2, a3;
                    uint32_t ad = sAl + SWZ((wm0 + (mt << 4) + lr) * 128 + kb + lc);
                    LDSM4(a0, a1, a2, a3, ad);
                    #pragma unroll
                    for (int n8 = 0; n8 < 4; n8++) {
                        int bt = n8 >> 1, nn = n8 & 1;
                        MMA16816(acc[mt][n8], a0, a1, a2, a3, bh[bt][nn], bh[bt][nn + 2]);
                    }
                }
            }
            __syncthreads();
        }

        // epilogue
        #pragma unroll
        for (int mt = 0; mt < 4; mt++) {
            int o = wm0 + (mt << 4) + (lid >> 2);
            float* rp = out + (((size_t)((b << 8) + o)) << 12) + pin;
            #pragma unroll
            for (int n8 = 0; n8 < 4; n8++) {
                int col = wn0 + (n8 << 3) + ((lid & 3) << 1);
                *(float2*)(rp + col)             = make_float2(acc[mt][n8][0], acc[mt][n8][1]);
                *(float2*)(rp + (8 << 12) + col) = make_float2(acc[mt][n8][2], acc[mt][n8][3]);
            }
        }
    } else {
        for (int s = 0; s < NST2; s++) {
            if (s + 1 < NST2)
                produceP(s + 1, t2, sb, b, pin);
            __syncthreads();
        }
    }
}

// ---------------------------------------------------------------------------
extern "C" void kernel_launch(void* const* d_in, const int* in_sizes, int n_in,
                              void* d_out, int out_size) {
    const float* x   = (const float*)d_in[0];
    const float* off = (const float*)d_in[1];
    const float* w   = (const float*)d_in[2];
    float* out = (float*)d_out;

    cudaFuncSetAttribute(dconv_fused,
                         cudaFuncAttributeMaxDynamicSharedMemorySize, SM_TOTAL);

    aprep_kernel<<<(COUT*KJ + 255) / 256, 256>>>(w);
    meta_kernel<<<(BB*K2*PLANE + 255) / 256, 256>>>(off);
    xt_kernel<<<BB * 128 * 8, 256>>>(x);

    dconv_fused<<<NPIX / 128, 640, SM_TOTAL>>>(out);
}

// round 10
// speedup vs baseline: 1.2560x; 1.0287x over previous
#include <cuda_runtime.h>
#include <cstdint>

// Problem constants
#define BB   8
#define C    256
#define HH   64
#define WW   64
#define K2   9
#define COUT 256
#define PLANE (HH*WW)      // 4096
#define NPIX  (BB*PLANE)   // 32768
#define KJ   2304          // C*K2

// ---------------------------------------------------------------------------
// Static device scratch
// ---------------------------------------------------------------------------
__device__ float g_mw0[BB*K2*PLANE];
__device__ float g_mw1[BB*K2*PLANE];
__device__ float g_mw2[BB*K2*PLANE];
__device__ float g_mw3[BB*K2*PLANE];
__device__ int   g_mi0[BB*K2*PLANE];
__device__ int   g_mi1[BB*K2*PLANE];
__device__ int   g_mi2[BB*K2*PLANE];
__device__ int   g_mi3[BB*K2*PLANE];

// Weights bf16, 2 planes: [plane][o][j]  (plane0=hi, plane1=lo), j = k9*256+c
__device__ __align__(16) unsigned short g_A[2 * COUT * KJ];

// x transposed to NHWC: g_xt[((b*4096 + pix) * 256) + c]
__device__ __align__(16) float g_xt[(size_t)NPIX * C];     // 134 MB

// ---------------------------------------------------------------------------
__device__ __forceinline__ void bsplit(float v, unsigned &h, unsigned &l) {
    unsigned u = __float_as_uint(v);
    unsigned r = (u + 0x7FFFu + ((u >> 16) & 1u)) & 0xFFFF0000u;
    h = r >> 16;
    float d = v - __uint_as_float(r);
    unsigned ud = __float_as_uint(d);
    l = (ud + 0x7FFFu + ((ud >> 16) & 1u)) >> 16;
}

// ---------------------------------------------------------------------------
// Kernel 1: weight prep
// ---------------------------------------------------------------------------
__global__ void aprep_kernel(const float* __restrict__ w) {
    int idx = blockIdx.x * 256 + threadIdx.x;
    if (idx >= COUT * KJ) return;
    int o = idx / KJ;
    int j = idx - o * KJ;
    int c = j & 255, k9 = j >> 8;
    float v = w[((o << 8) + c) * 9 + k9];
    unsigned h, l; bsplit(v, h, l);
    g_A[idx]             = (unsigned short)h;
    g_A[COUT*KJ + idx]   = (unsigned short)l;
}

// ---------------------------------------------------------------------------
// Kernel 2: bilinear metadata
// ---------------------------------------------------------------------------
__global__ void meta_kernel(const float* __restrict__ off) {
    int e = blockIdx.x * 256 + threadIdx.x;
    if (e >= BB*K2*PLANE) return;
    int p  = e & (PLANE - 1);
    int bk = e >> 12;
    int k  = bk % 9;
    int b  = bk / 9;
    int ho = p >> 6;
    int wo = p & 63;

    float dy = off[((size_t)(b*18 + 2*k    ) << 12) + p];
    float dx = off[((size_t)(b*18 + 2*k + 1) << 12) + p];

    float py = (float)(ho - 1 + (k / 3)) + dy;
    float px = (float)(wo - 1 + (k % 3)) + dx;

    float y0f = floorf(py), x0f = floorf(px);
    float fy = py - y0f, fx = px - x0f;
    int   y0 = (int)y0f,  x0 = (int)x0f;

    float wy[2] = {1.0f - fy, fy};
    float wx[2] = {1.0f - fx, fx};
    int   ys[2] = {y0, y0 + 1};
    int   xs[2] = {x0, x0 + 1};

    float mw[4]; int mi[4];
    #pragma unroll
    for (int jy = 0; jy < 2; jy++)
        #pragma unroll
        for (int jx = 0; jx < 2; jx++) {
            int jj = jy*2 + jx;
            int cy = ys[jy], cx = xs[jx];
            bool valid = (cy >= 0) && (cy < HH) && (cx >= 0) && (cx < WW);
            float wgt = valid ? wy[jy] * wx[jx] : 0.0f;
            int iy = min(max(cy, 0), HH - 1);
            int ix = min(max(cx, 0), WW - 1);
            mw[jj] = wgt;
            mi[jj] = iy * WW + ix;
        }
    g_mw0[e] = mw[0]; g_mw1[e] = mw[1]; g_mw2[e] = mw[2]; g_mw3[e] = mw[3];
    g_mi0[e] = mi[0]; g_mi1[e] = mi[1]; g_mi2[e] = mi[2]; g_mi3[e] = mi[3];
}

// ---------------------------------------------------------------------------
// Kernel 3: NCHW -> NHWC transpose (32x32 tiles via smem)
// ---------------------------------------------------------------------------
__global__ __launch_bounds__(256)
void xt_kernel(const float* __restrict__ x) {
    __shared__ float ts[32][33];
    int bid = blockIdx.x;
    int ct = (bid & 7) << 5;
    int pt = ((bid >> 3) & 127) << 5;
    int b  = bid >> 10;
    int l0 = threadIdx.x & 31;
    int l1 = threadIdx.x >> 5;
    const float* xb = x + ((size_t)b << 20);
    #pragma unroll
    for (int r = 0; r < 4; r++) {
        int c = ct + l1 + r * 8;
        ts[l1 + r * 8][l0] = xb[((size_t)c << 12) + pt + l0];
    }
    __syncthreads();
    float* xo = g_xt + (((size_t)(b << 12) + pt) << 8) + ct;
    #pragma unroll
    for (int r = 0; r < 4; r++) {
        int p = l1 + r * 8;
        xo[((size_t)p << 8) + l0] = ts[l0][p];
    }
}

// ---------------------------------------------------------------------------
// Kernel 4: fused warp-specialized GEMM with split named barriers
//   640 threads: warps 0-15 MMA consumers; warps 16-19 producers.
//   barrier 0: tile-ready (producers arrive, consumers sync)
//   barrier 1: tile-consumed (consumers arrive, producer syncs at sn>=2)
// ---------------------------------------------------------------------------
#define SWZ(x) ((x) ^ (((x) >> 3) & 0x70))
#define NST2   36
#define SM_TOTAL 196608

static __device__ __forceinline__ uint32_t smem_u32(const void* p) {
    uint32_t a;
    asm("{ .reg .u64 t; cvta.to.shared.u64 t, %1; cvt.u32.u64 %0, t; }"
        : "=r"(a) : "l"(p));
    return a;
}
static __device__ __forceinline__ void cp16(uint32_t dst, const void* src) {
    asm volatile("cp.async.cg.shared.global [%0], [%1], 16;\n"
                 :: "r"(dst), "l"(src));
}
#define LDSM4(r0, r1, r2, r3, a)                                              \
    asm volatile("ldmatrix.sync.aligned.m8n8.x4.shared.b16 {%0,%1,%2,%3}, [%4];" \
                 : "=r"(r0), "=r"(r1), "=r"(r2), "=r"(r3) : "r"(a))
#define MMA16816(d, a0, a1, a2, a3, b0, b1)                                   \
    asm volatile("mma.sync.aligned.m16n8k16.row.col.f32.bf16.bf16.f32 "       \
                 "{%0,%1,%2,%3}, {%4,%5,%6,%7}, {%8,%9}, {%0,%1,%2,%3};"      \
                 : "+f"((d)[0]), "+f"((d)[1]), "+f"((d)[2]), "+f"((d)[3])     \
                 : "r"(a0), "r"(a1), "r"(a2), "r"(a3), "r"(b0), "r"(b1))
#define STS64(a, v0, v1)                                                      \
    asm volatile("st.shared.v2.b32 [%0], {%1,%2};"                            \
                 :: "r"(a), "r"(v0), "r"(v1) : "memory")
#define BAR_SYNC(id)   asm volatile("bar.sync %0, 640;"   :: "r"(id) : "memory")
#define BAR_ARRIVE(id) asm volatile("bar.arrive %0, 640;" :: "r"(id) : "memory")

// Producer: build stage sn into slot sn&1 (A via cp.async, B via NHWC gather)
static __device__ __forceinline__ void produceP(int sn, int t2, uint32_t sb,
                                                int b, int pin) {
    // ---- A (hi+lo, 64 KB) via cp.async ----
    {
        uint32_t dst0 = sb + (sn & 1) * 65536;
        #pragma unroll
        for (int i = 0; i < 32; i++) {
            int id = t2 + (i << 7);          // 0..4095
            int pl = id >> 11;
            int idp = id & 2047;
            int row = idp >> 3;
            int kb = (idp & 7) << 4;
            const char* src = (const char*)g_A +
                (((size_t)(pl * COUT + row) * KJ + sn * 64) << 1) + kb;
            cp16(dst0 + pl * 32768 + SWZ(row * 128 + kb), src);
        }
        asm volatile("cp.async.commit_group;" ::: "memory");
    }
    // ---- B gather from NHWC, coalesced: 16 lanes cover one 256B ch-row ----
    int k9 = sn >> 2, cb = (sn & 3) << 6;
    int pw = t2 >> 5, lane = t2 & 31;
    int phalf = lane >> 4, lane4 = lane & 15;
    uint32_t sBh = sb + 131072 + (sn & 1) * 32768;
    uint32_t sBl = sBh + 16384;
    const float* xb = g_xt + (((size_t)(b << 12)) << 8) + cb + (lane4 << 2);

    #pragma unroll
    for (int it = 0; it < 16; it++) {
        int px = (it << 3) + (pw << 1) + phalf;
        int e = ((b * 9 + k9) << 12) + pin + px;
        float w0 = g_mw0[e], w1 = g_mw1[e], w2 = g_mw2[e], w3 = g_mw3[e];
        int   i0 = g_mi0[e], i1 = g_mi1[e], i2 = g_mi2[e], i3 = g_mi3[e];
        float4 f0 = *(const float4*)(xb + ((size_t)i0 << 8));
        float4 f1 = *(const float4*)(xb + ((size_t)i1 << 8));
        float4 f2 = *(const float4*)(xb + ((size_t)i2 << 8));
        float4 f3 = *(const float4*)(xb + ((size_t)i3 << 8));
        float v0 = w0*f0.x + w1*f1.x + w2*f2.x + w3*f3.x;
        float v1 = w0*f0.y + w1*f1.y + w2*f2.y + w3*f3.y;
        float v2 = w0*f0.z + w1*f1.z + w2*f2.z + w3*f3.z;
        float v3 = w0*f0.w + w1*f1.w + w2*f2.w + w3*f3.w;
        unsigned u0 = __float_as_uint(v0), u1 = __float_as_uint(v1);
        unsigned u2 = __float_as_uint(v2), u3 = __float_as_uint(v3);
        float e0 = v0 - __uint_as_float(u0 & 0xFFFF0000u);
        float e1 = v1 - __uint_as_float(u1 & 0xFFFF0000u);
        float e2 = v2 - __uint_as_float(u2 & 0xFFFF0000u);
        float e3 = v3 - __uint_as_float(u3 & 0xFFFF0000u);
        unsigned h01 = __byte_perm(u0, u1, 0x7632);
        unsigned h23 = __byte_perm(u2, u3, 0x7632);
        unsigned l01 = __byte_perm(__float_as_uint(e0), __float_as_uint(e1), 0x7632);
        unsigned l23 = __byte_perm(__float_as_uint(e2), __float_as_uint(e3), 0x7632);
        int boff = (px << 7) + (lane4 << 3);
        STS64(sBh + SWZ(boff), h01, h23);
        STS64(sBl + SWZ(boff), l01, l23);
    }
    asm volatile("cp.async.wait_group 0;" ::: "memory");
}

__global__ __launch_bounds__(640, 1)
void dconv_fused(float* __restrict__ out) {
    extern __shared__ char smem[];
    uint32_t sb = smem_u32(smem);
    int tid = threadIdx.x;
    int wid = tid >> 5, lid = tid & 31;
    const int pt0 = blockIdx.x << 7;
    const int b = pt0 >> 12;
    const int pin = pt0 & 4095;

    if (tid >= 512) {
        // ---------------- producer warps ----------------
        int t2 = tid - 512;
        for (int sn = 0; sn < NST2; sn++) {
            if (sn >= 2) BAR_SYNC(1);            // wait consumers done with slot
            produceP(sn, t2, sb, b, pin);
            BAR_ARRIVE(0);                       // tile sn ready
        }
        return;
    }

    // ---------------- consumer warps ----------------
    const int wm0 = (wid & 3) << 6;
    const int wn0 = (wid >> 2) << 5;
    float acc[4][4][4];
    #pragma unroll
    for (int i = 0; i < 4; i++)
        #pragma unroll
        for (int j = 0; j < 4; j++)
            #pragma unroll
            for (int r = 0; r < 4; r++) acc[i][j][r] = 0.0f;

    int lr = lid & 15, lc = (lid >> 4) << 4;

    for (int s = 0; s < NST2; s++) {
        BAR_SYNC(0);                             // wait tile s ready
        uint32_t base = sb + (s & 1) * 65536;
        uint32_t sAh = base, sAl = base + 32768;
        uint32_t sBh = sb + 131072 + (s & 1) * 32768;
        uint32_t sBl = sBh + 16384;

        #pragma unroll
        for (int ks = 0; ks < 4; ks++) {
            int kb = ks << 5;
            uint32_t bh[2][4], bl[2][4];
            #pragma unroll
            for (int bt = 0; bt < 2; bt++) {
                uint32_t bd = sBh + SWZ((wn0 + (bt << 4) + lr) * 128 + kb + lc);
                LDSM4(bh[bt][0], bh[bt][1], bh[bt][2], bh[bt][3], bd);
            }
            #pragma unroll
            for (int bt = 0; bt < 2; bt++) {
                uint32_t bd = sBl + SWZ((wn0 + (bt << 4) + lr) * 128 + kb + lc);
                LDSM4(bl[bt][0], bl[bt][1], bl[bt][2], bl[bt][3], bd);
            }
            #pragma unroll
            for (int mt = 0; mt < 4; mt++) {
                uint32_t a0, a1, a2, a3;
                uint32_t ad = sAh + SWZ((wm0 + (mt << 4) + lr) * 128 + kb + lc);
                LDSM4(a0, a1, a2, a3, ad);
                #pragma unroll
                for (int n8 = 0; n8 < 4; n8++) {
                    int bt = n8 >> 1, nn = n8 & 1;
                    MMA16816(acc[mt][n8], a0, a1, a2, a3, bh[bt][nn], bh[bt][nn + 2]);
                }
                #pragma unroll
                for (int n8 = 0; n8 < 4; n8++) {
                    int bt = n8 >> 1, nn = n8 & 1;
                    MMA16816(acc[mt][n8], a0, a1, a2, a3, bl[bt][nn], bl[bt][nn + 2]);
                }
            }
            #pragma unroll
            for (int mt = 0; mt < 4; mt++) {
                uint32_t a0, a1, a2, a3;
                uint32_t ad = sAl + SWZ((wm0 + (mt << 4) + lr) * 128 + kb + lc);
                LDSM4(a0, a1, a2, a3, ad);
                #pragma unroll
                for (int n8 = 0; n8 < 4; n8++) {
                    int bt = n8 >> 1, nn = n8 & 1;
                    MMA16816(acc[mt][n8], a0, a1, a2, a3, bh[bt][nn], bh[bt][nn + 2]);
                }
            }
        }
        if (s + 2 < NST2) BAR_ARRIVE(1);         // slot s&1 free for reuse
    }

    // epilogue
    #pragma unroll
    for (int mt = 0; mt < 4; mt++) {
        int o = wm0 + (mt << 4) + (lid >> 2);
        float* rp = out + (((size_t)((b << 8) + o)) << 12) + pin;
        #pragma unroll
        for (int n8 = 0; n8 < 4; n8++) {
            int col = wn0 + (n8 << 3) + ((lid & 3) << 1);
            *(float2*)(rp + col)             = make_float2(acc[mt][n8][0], acc[mt][n8][1]);
            *(float2*)(rp + (8 << 12) + col) = make_float2(acc[mt][n8][2], acc[mt][n8][3]);
        }
    }
}

// ---------------------------------------------------------------------------
extern "C" void kernel_launch(void* const* d_in, const int* in_sizes, int n_in,
                              void* d_out, int out_size) {
    const float* x   = (const float*)d_in[0];
    const float* off = (const float*)d_in[1];
    const float* w   = (const float*)d_in[2];
    float* out = (float*)d_out;

    cudaFuncSetAttribute(dconv_fused,
                         cudaFuncAttributeMaxDynamicSharedMemorySize, SM_TOTAL);

    aprep_kernel<<<(COUT*KJ + 255) / 256, 256>>>(w);
    meta_kernel<<<(BB*K2*PLANE + 255) / 256, 256>>>(off);
    xt_kernel<<<BB * 128 * 8, 256>>>(x);

    dconv_fused<<<NPIX / 128, 640, SM_TOTAL>>>(out);
}